// round 1
// baseline (speedup 1.0000x reference)
#include <cuda_runtime.h>

// Problem constants (fixed by the reference)
#define BB    256        // batch
#define TT    16384      // series length
#define WIN   5
#define HID   5
#define NN    (TT - WIN) // 16379 positions
#define NP    16384      // padded stride for partial buffer

#define GROUPS 32        // b-groups (grid.y)
#define BPG    (BB / GROUPS)  // 8 b per group
#define NPT    8         // n per thread
#define TPB    256
#define NPB    (NPT * TPB)          // 2048 n per block
#define NTILES ((NN + NPB - 1) / NPB) // 8 tiles

// Scratch: per-group partial loss sums. 32 * 16384 * 4B = 2 MB.
__device__ float g_partial[GROUPS * NP];

__global__ void __launch_bounds__(TPB)
llsa_main_kernel(const float* __restrict__ series,
                 const float* __restrict__ weight,
                 const float* __restrict__ bias)
{
    const int tile = blockIdx.x;
    const int g    = blockIdx.y;
    const int t    = threadIdx.x;
    const int n0   = tile * NPB + t * NPT;

    // Load the 5x5 weight + bias into registers (L2/L1 hits after first warp).
    float W[HID][WIN], bv[HID];
#pragma unroll
    for (int h = 0; h < HID; h++) {
        bv[h] = __ldg(&bias[h]);
#pragma unroll
        for (int w = 0; w < WIN; w++)
            W[h][w] = __ldg(&weight[h * WIN + w]);
    }

    float acc[NPT];
#pragma unroll
    for (int i = 0; i < NPT; i++) acc[i] = 0.0f;

    const bool fast = (n0 + 16 <= TT);  // full float4x4 window in-bounds

    for (int bb = 0; bb < BPG; bb++) {
        const float* __restrict__ row = series + (size_t)(g * BPG + bb) * TT;

        float x[16];
        if (fast) {
            // n0 is a multiple of 8 -> 32B aligned, float4 loads are legal.
            const float4* p = reinterpret_cast<const float4*>(row + n0);
            float4 v0 = __ldg(&p[0]);
            float4 v1 = __ldg(&p[1]);
            float4 v2 = __ldg(&p[2]);
            float4 v3 = __ldg(&p[3]);
            x[0]=v0.x;  x[1]=v0.y;  x[2]=v0.z;  x[3]=v0.w;
            x[4]=v1.x;  x[5]=v1.y;  x[6]=v1.z;  x[7]=v1.w;
            x[8]=v2.x;  x[9]=v2.y;  x[10]=v2.z; x[11]=v2.w;
            x[12]=v3.x; x[13]=v3.y; x[14]=v3.z; x[15]=v3.w;
        } else {
            // Tail threads only (last tile, t == 255): scalar guarded loads.
#pragma unroll
            for (int j = 0; j < 16; j++)
                x[j] = (n0 + j < TT) ? __ldg(&row[n0 + j]) : 0.0f;
        }

#pragma unroll
        for (int i = 0; i < NPT; i++) {
            float s = 0.0f;
#pragma unroll
            for (int h = 0; h < HID; h++) {
                float th = bv[h];
#pragma unroll
                for (int w = 0; w < WIN; w++)
                    th = fmaf(W[h][w], x[i + w], th);
                float d = th - x[i + 1 + h];
                s = fmaf(d, d, s);
            }
            acc[i] += s;
        }
    }

#pragma unroll
    for (int i = 0; i < NPT; i++) {
        int n = n0 + i;
        if (n < NN) g_partial[g * NP + n] = acc[i];
    }
}

// Pairwise fp32 tree reduce of the 32 group partials for position n.
__device__ __forceinline__ float reduce_groups(int n)
{
    float v[GROUPS];
#pragma unroll
    for (int g = 0; g < GROUPS; g++)
        v[g] = g_partial[g * NP + n];
#pragma unroll
    for (int stride = GROUPS / 2; stride >= 1; stride >>= 1) {
#pragma unroll
        for (int g = 0; g < GROUPS / 2; g++)
            if (g < stride) v[g] = v[g] + v[g + stride];
    }
    return v[0];
}

__global__ void __launch_bounds__(256)
llsa_finalize_kernel(float* __restrict__ out,
                     const float* __restrict__ thr_p)
{
    const int n = blockIdx.x * blockDim.x + threadIdx.x;
    if (n >= NN) return;

    const float inv = 1.0f / (float)(BB * HID);

    float loss_n = reduce_groups(n) * inv;
    out[n] = loss_n;

    if (n + 1 < NN) {
        float loss_n1 = reduce_groups(n + 1) * inv;
        float d = fabsf(loss_n1 - loss_n);
        out[NN + n] = d;                                   // diffs
        out[NN + (NN - 1) + n] = (d > *thr_p) ? 1.0f : 0.0f; // change_mask
    }
}

extern "C" void kernel_launch(void* const* d_in, const int* in_sizes, int n_in,
                              void* d_out, int out_size)
{
    const float* series = (const float*)d_in[0];
    const float* weight = (const float*)d_in[1];
    const float* bias   = (const float*)d_in[2];
    const float* thr    = (const float*)d_in[3];
    float* out = (float*)d_out;

    dim3 grid(NTILES, GROUPS);
    llsa_main_kernel<<<grid, TPB>>>(series, weight, bias);

    llsa_finalize_kernel<<<(NN + 255) / 256, 256>>>(out, thr);
}